// round 4
// baseline (speedup 1.0000x reference)
#include <cuda_runtime.h>
#include <cuda_bf16.h>
#include <cstdint>

#define NCONCEPTS 4096
#define CDIM      1024
#define BATCH     4096
#define KSAMP     256

// Scratch for per-concept dot products (no cudaMalloc allowed).
__device__ float g_s[NCONCEPTS];

// Kernel 1: per-concept dots AND zero the entire output.
// 512 blocks x 256 threads. Each warp computes one dot row (8 rows/block);
// each block also zeroes 8 output rows (32K floats) with float4 stores.
// The zero stores are independent of the dots and overlap with the
// 577-cycle DRAM load latency of the dot reads.
__global__ void __launch_bounds__(256) dot_and_zero_kernel(
    const float* __restrict__ cb,
    const float* __restrict__ at,
    float* __restrict__ out)
{
    const int warp = threadIdx.x >> 5;
    const int lane = threadIdx.x & 31;
    const int row  = blockIdx.x * 8 + warp;

    const float4* __restrict__ a = reinterpret_cast<const float4*>(cb + (size_t)row * CDIM);
    const float4* __restrict__ b = reinterpret_cast<const float4*>(at + (size_t)row * CDIM);

    float acc = 0.0f;
#pragma unroll
    for (int i = 0; i < CDIM / 4 / 32; ++i) {   // 8 iterations
        float4 x = a[lane + i * 32];
        float4 y = b[lane + i * 32];
        acc += x.x * y.x + x.y * y.y + x.z * y.z + x.w * y.w;
    }

    // Zero 8 output rows per block: 32768 floats = 8192 float4 / 256 threads.
    {
        float4* __restrict__ z4 =
            reinterpret_cast<float4*>(out + (size_t)blockIdx.x * 8 * NCONCEPTS);
        const float4 z = make_float4(0.f, 0.f, 0.f, 0.f);
#pragma unroll
        for (int i = 0; i < 8 * NCONCEPTS / 4 / 256; ++i)   // 32 iterations
            z4[threadIdx.x + i * 256] = z;
    }

#pragma unroll
    for (int off = 16; off > 0; off >>= 1)
        acc += __shfl_xor_sync(0xffffffffu, acc, off);

    if (lane == 0)
        g_s[row] = acc;
}

// Kernel 2: pure scatter. Each thread handles 4 samples (int4 idx load).
// Stores hit L2 lines still dirty from kernel 1's zeroing.
// sampled_idx is int32 on-device (JAX default x32 downcasts the int64 request).
// Duplicate indices write the same value -> benign.
__global__ void __launch_bounds__(256) scatter_kernel(
    const int4* __restrict__ idx4,
    float* __restrict__ out)
{
    const int t = blockIdx.x * blockDim.x + threadIdx.x;   // 0 .. BATCH*KSAMP/4-1
    const int b = t >> 6;                                   // 64 int4 per row (256 idx)
    const int4 c = idx4[t];

    float* __restrict__ row = out + (size_t)b * NCONCEPTS;
    row[c.x] = g_s[c.x];
    row[c.y] = g_s[c.y];
    row[c.z] = g_s[c.z];
    row[c.w] = g_s[c.w];
}

extern "C" void kernel_launch(void* const* d_in, const int* in_sizes, int n_in,
                              void* d_out, int out_size)
{
    const float* cb  = (const float*)d_in[0];
    const float* at  = (const float*)d_in[1];
    const int4*  idx = (const int4*)d_in[2];
    float*       out = (float*)d_out;

    dot_and_zero_kernel<<<NCONCEPTS / 8, 256>>>(cb, at, out);
    scatter_kernel<<<(BATCH * KSAMP / 4) / 256, 256>>>(idx, out);
}

// round 8
// speedup vs baseline: 1.0105x; 1.0105x over previous
#include <cuda_runtime.h>
#include <cuda_bf16.h>
#include <cstdint>

#define NCONCEPTS 4096
#define CDIM      1024
#define BATCH     4096
#define KSAMP     256

// Scratch for per-concept dot products (no cudaMalloc allowed).
__device__ float g_s[NCONCEPTS];

// Kernel 1: one warp per concept row: s[c] = sum_d cb[c,d] * A[c,d]
__global__ void __launch_bounds__(256) dot_rows_kernel(
    const float* __restrict__ cb,
    const float* __restrict__ at)
{
    const int row  = blockIdx.x * 8 + (threadIdx.x >> 5);
    const int lane = threadIdx.x & 31;

    const float4* __restrict__ a = reinterpret_cast<const float4*>(cb + (size_t)row * CDIM);
    const float4* __restrict__ b = reinterpret_cast<const float4*>(at + (size_t)row * CDIM);

    float acc = 0.0f;
#pragma unroll
    for (int i = 0; i < CDIM / 4 / 32; ++i) {   // 8 iterations
        float4 x = a[lane + i * 32];
        float4 y = b[lane + i * 32];
        acc += x.x * y.x + x.y * y.y + x.z * y.z + x.w * y.w;
    }
#pragma unroll
    for (int off = 16; off > 0; off >>= 1)
        acc += __shfl_xor_sync(0xffffffffu, acc, off);

    if (lane == 0)
        g_s[row] = acc;
}

// Kernel 2: one block per batch row. Build the row in shared memory
// (zero + scatter of 256 values), then write it out with fully
// coalesced 128B-line float4 stores. No random global stores at all.
// The idx -> g_s dependent-load chain is hoisted above the zero phase
// so its ~600-cycle latency hides under the smem stores.
// sampled_idx is int32 on-device (JAX default x32 downcasts the int64 request).
// Duplicate indices write the same value -> benign.
__global__ void __launch_bounds__(256) row_build_kernel(
    const int* __restrict__ idx,
    float* __restrict__ out)
{
    __shared__ float srow[NCONCEPTS];

    const int b = blockIdx.x;
    const int t = threadIdx.x;

    // Hoisted loads: start the dependent idx -> g_s chain immediately.
    const int   c = idx[b * KSAMP + t];
    const float v = g_s[c];

    // Phase 1: zero the smem row (4096 floats / 256 threads, float4).
    float4* __restrict__ s4 = reinterpret_cast<float4*>(srow);
    const float4 z = make_float4(0.f, 0.f, 0.f, 0.f);
#pragma unroll
    for (int i = 0; i < NCONCEPTS / 4 / 256; ++i)   // 4 iterations
        s4[t + i * 256] = z;

    __syncthreads();

    // Phase 2: scatter into smem (random STS, cheap).
    srow[c] = v;

    __syncthreads();

    // Phase 3: coalesced write-out of the full row.
    float4* __restrict__ o4 = reinterpret_cast<float4*>(out + (size_t)b * NCONCEPTS);
#pragma unroll
    for (int i = 0; i < NCONCEPTS / 4 / 256; ++i)   // 4 iterations
        o4[t + i * 256] = s4[t + i * 256];
}

extern "C" void kernel_launch(void* const* d_in, const int* in_sizes, int n_in,
                              void* d_out, int out_size)
{
    const float* cb  = (const float*)d_in[0];
    const float* at  = (const float*)d_in[1];
    const int*   idx = (const int*)d_in[2];
    float*       out = (float*)d_out;

    dot_rows_kernel<<<NCONCEPTS / 8, 256>>>(cb, at);
    row_build_kernel<<<BATCH, 256>>>(idx, out);
}